// round 9
// baseline (speedup 1.0000x reference)
#include <cuda_runtime.h>
#include <cuda_fp16.h>
#include <cstdint>

// ---------------------------------------------------------------------------
// Problem constants
// ---------------------------------------------------------------------------
#define BATCH    8192
#define HIDDEN   2048
#define NQ       16
#define HALF_DIM 1024

// GEMM tiling: CTA 128(M)x64(N), 4 warps (2Mx2N of 64x32), 4 CTAs/SM.
// A: cp.async -> SW128 smem (3 stages) -> ldmatrix.
// B: fragment-major gmem layout -> LDG.64 straight to registers (no smem).
#define BM      128
#define BN      64
#define KC      64                      // fp16 K elements per chunk
#define NCHUNK  (HIDDEN / KC)           // 32
#define THREADS 128
#define M_TILES (BATCH / BM)            // 64
#define N_TILES (NQ * HALF_DIM / BN)    // 256
#define NTILES  (M_TILES * N_TILES)     // 16384

#define A_STAGE_BYTES (BM * KC * 2)     // 16384
#define ASTAGES 3

// SMEM layout (dynamic)
#define OFF_PAR   0                     // 128 floats (b1 | w2)
#define OFF_STAGE 1024
#define SMEM_BYTES (OFF_STAGE + ASTAGES * A_STAGE_BYTES)  // 50176 (x4 = 196KB/SM)

// B fragment-major layout strides (bytes):
//   record(k16, n8) = 32 lanes x 8B; addr = ((k16*2048 + n8)*32 + lane)*8
#define B_K16_STRIDE 524288u            // 2048 * 32 * 8
#define B_CHUNK_STRIDE (4u * B_K16_STRIDE)

// fp16 scratch (device globals: allocation-free scratch per harness rules)
__device__ __align__(1024) __half g_Xh[(size_t)BATCH * HIDDEN];            // 32 MB
__device__ __align__(1024) __half g_Wf[(size_t)NQ * HALF_DIM * HIDDEN];   // 64 MB

// ---------------------------------------------------------------------------
// Helpers
// ---------------------------------------------------------------------------
__device__ __forceinline__ uint32_t smem_u32(const void* p) {
    uint32_t a;
    asm("{ .reg .u64 t; cvta.to.shared.u64 t, %1; cvt.u32.u64 %0, t; }"
        : "=r"(a) : "l"(p));
    return a;
}

#define SW128(off) ((off) ^ (((off) >> 3) & 0x70))

__device__ __forceinline__ void cp_async16(uint32_t dst, const void* src) {
    asm volatile("cp.async.cg.shared.global [%0], [%1], 16;" :: "r"(dst), "l"(src) : "memory");
}
__device__ __forceinline__ void cp_async_commit() {
    asm volatile("cp.async.commit_group;" ::: "memory");
}
template <int N>
__device__ __forceinline__ void cp_async_wait() {
    asm volatile("cp.async.wait_group %0;" :: "n"(N) : "memory");
}

__device__ __forceinline__ void ldsm4(uint32_t* r, uint32_t addr) {
    asm volatile("ldmatrix.sync.aligned.m8n8.x4.shared.b16 {%0,%1,%2,%3}, [%4];"
        : "=r"(r[0]), "=r"(r[1]), "=r"(r[2]), "=r"(r[3]) : "r"(addr));
}

__device__ __forceinline__ void mma16816(float* c, const uint32_t* a, uint2 b) {
    asm volatile(
        "mma.sync.aligned.m16n8k16.row.col.f32.f16.f16.f32 "
        "{%0,%1,%2,%3}, {%4,%5,%6,%7}, {%8,%9}, {%0,%1,%2,%3};"
        : "+f"(c[0]), "+f"(c[1]), "+f"(c[2]), "+f"(c[3])
        : "r"(a[0]), "r"(a[1]), "r"(a[2]), "r"(a[3]), "r"(b.x), "r"(b.y));
}

// ---------------------------------------------------------------------------
// Prepass kernels
// ---------------------------------------------------------------------------
__global__ void prep_x_kernel(const float4* __restrict__ x, int n4) {
    int i = blockIdx.x * blockDim.x + threadIdx.x;
    if (i < n4) {
        float4 v = x[i];
        __half2 lo = __floats2half2_rn(v.x, v.y);
        __half2 hi = __floats2half2_rn(v.z, v.w);
        union { __half2 h; unsigned u; } a, b;
        a.h = lo; b.h = hi;
        reinterpret_cast<uint2*>(g_Xh)[i] = make_uint2(a.u, b.u);
    }
}

// W1[q][k][n] (n contiguous) -> fragment-major B for mma.m16n8k16 row.col:
// record (k16, n8): lane l holds reg0 = {B[k=2(l&3)][n=l>>2], B[k+1][n]},
// reg1 = {B[k+8][n], B[k+9][n]} (k,n relative to block), value = W1[k][n].
__global__ void prep_wf_kernel(const float* __restrict__ W1) {
    int n8   = blockIdx.x;                               // 0..2047
    int k16  = blockIdx.y * 32 + (threadIdx.x >> 5);     // 0..127
    int lane = threadIdx.x & 31;
    int q = n8 >> 7;
    int n = ((n8 & 127) << 3) + (lane >> 2);
    const float* src = W1 + (size_t)q * HIDDEN * HALF_DIM + n;
    int kb = (k16 << 4) + ((lane & 3) << 1);
    float v0 = src[(size_t)(kb + 0) * HALF_DIM];
    float v1 = src[(size_t)(kb + 1) * HALF_DIM];
    float v2 = src[(size_t)(kb + 8) * HALF_DIM];
    float v3 = src[(size_t)(kb + 9) * HALF_DIM];
    union { __half2 h; uint32_t u; } r0, r1;
    r0.h = __floats2half2_rn(v0, v1);   // lo = lower k
    r1.h = __floats2half2_rn(v2, v3);
    reinterpret_cast<uint2*>(g_Wf)[((size_t)k16 * 2048 + n8) * 32 + lane] =
        make_uint2(r0.u, r1.u);
}

__global__ void init_out_kernel(float* __restrict__ out, const float* __restrict__ b2) {
    int i = blockIdx.x * blockDim.x + threadIdx.x;
    if (i < BATCH * NQ) out[i] = b2[i & (NQ - 1)];
}

// ---------------------------------------------------------------------------
// A stage load (A only): per-thread constant offsets, only base ptr varies.
// ---------------------------------------------------------------------------
__device__ __forceinline__ void load_stageA(uint32_t a0, uint32_t sw, const char* ga) {
#pragma unroll
    for (int t = 0; t < 8; t++)
        cp_async16(a0 + sw + t * 2048, ga + (size_t)t * (16 * HIDDEN * 2));
}

// ---------------------------------------------------------------------------
// Main GEMM + fused GELU/GEMV epilogue
// ---------------------------------------------------------------------------
__global__ void __launch_bounds__(THREADS, 4)
gemm_kernel(const float* __restrict__ b1, const float* __restrict__ W2,
            float* __restrict__ out) {
    extern __shared__ char smem[];
    const uint32_t sb = smem_u32(smem);
    const int tid = threadIdx.x;
    const int wid = tid >> 5;
    const int lid = tid & 31;
    const int wm  = wid >> 1;           // M slab (64 rows), 0..1
    const int wn  = wid & 1;            // N slab (32 cols), 0..1

    // Per-thread cp.async offsets (t-invariant swizzle: row&7 fixed)
    const uint32_t ld_sw  = SW128((uint32_t)((tid >> 3) * 128 + (tid & 7) * 16));
    const size_t   ld_off = (size_t)(tid >> 3) * (HIDDEN * 2) + (tid & 7) * 16;

    // A LDSM base offset: addr = stage_base + ((a_l0 + mi*2048) ^ (kk<<5))
    const uint32_t a_l0 = SW128((uint32_t)((wm * 64 + (lid & 15)) * 128 + ((lid >> 4) << 4)));

    // Supertile swizzle: 8(M) x 16(N) CTAs per 128-CTA group
    int cta    = blockIdx.x;
    int super  = cta >> 7;
    int within = cta & 127;
    int m_tile = (super & 7) * 8 + (within & 7);     // 0..63
    int n_tile = (super >> 3) * 16 + (within >> 3);  // 0..255
    int m0     = m_tile * BM;
    int q      = n_tile >> 4;
    int nn     = (n_tile & 15) * BN;

    const char* Ab = (const char*)(g_Xh + (size_t)m0 * HIDDEN) + ld_off;
    // B fragment pointer for this warp/lane: n8 base = n_tile*8 + wn*4
    const char* Bp = (const char*)g_Wf
                   + (((size_t)(n_tile * 8 + wn * 4) * 32 + lid) << 3);

    // Epilogue params into smem (ordered before epilogue by chunk-loop syncs)
    {
        int col = tid & 63;
        const float* src = (tid < 64) ? b1 : W2;
        ((float*)smem)[tid] = src[q * HALF_DIM + nn + col];
    }

    // Prologue: A chunks 0,1 into stages 0,1
    load_stageA(sb + OFF_STAGE, ld_sw, Ab);
    cp_async_commit();
    load_stageA(sb + OFF_STAGE + A_STAGE_BYTES, ld_sw, Ab + KC * 2);
    cp_async_commit();

    // Prologue: B k16=0 into buffer 0
    uint2 bfr0[4], bfr1[4];
#pragma unroll
    for (int nj = 0; nj < 4; nj++)
        bfr0[nj] = reinterpret_cast<const uint2*>(Bp)[nj * 32];

    float acc[4][4][4];
#pragma unroll
    for (int mi = 0; mi < 4; mi++)
#pragma unroll
        for (int nj = 0; nj < 4; nj++)
#pragma unroll
            for (int e = 0; e < 4; e++) acc[mi][nj][e] = 0.0f;

    int amod = 0;   // stage holding chunk i
    int lmod = 2;   // stage receiving chunk i+2

    for (int i = 0; i < NCHUNK; i++) {
        if (i < NCHUNK - 2) cp_async_wait<1>();
        else                cp_async_wait<0>();
        __syncthreads();

        if (i + 2 < NCHUNK) {
            load_stageA(sb + OFF_STAGE + lmod * A_STAGE_BYTES, ld_sw,
                        Ab + (size_t)(i + 2) * (KC * 2));
            cp_async_commit();
        }

        uint32_t a_base = sb + OFF_STAGE + amod * A_STAGE_BYTES;
        amod = (amod == 2) ? 0 : amod + 1;
        lmod = (lmod == 2) ? 0 : lmod + 1;

#pragma unroll
        for (int kk = 0; kk < 4; kk++) {
            uint2* curb = (kk & 1) ? bfr1 : bfr0;
            uint2* nxtb = (kk & 1) ? bfr0 : bfr1;
            // Prefetch next k16's B fragments (barrier-independent)
            if (kk < 3 || i < NCHUNK - 1) {
                const uint2* p = reinterpret_cast<const uint2*>(
                    Bp + (size_t)(kk + 1) * B_K16_STRIDE);
#pragma unroll
                for (int nj = 0; nj < 4; nj++) nxtb[nj] = p[nj * 32];
            }
            uint32_t afr[4][4];
#pragma unroll
            for (int mi = 0; mi < 4; mi++)
                ldsm4(afr[mi], a_base + ((a_l0 + mi * 2048) ^ (kk << 5)));
#pragma unroll
            for (int mi = 0; mi < 4; mi++)
#pragma unroll
                for (int nj = 0; nj < 4; nj++)
                    mma16816(acc[mi][nj], afr[mi], curb[nj]);
        }
        Bp += B_CHUNK_STRIDE;
    }

    // Epilogue: h = acc + b1; gelu(h) = h * Phi(h); dot with W2; quad-reduce.
    const float* b1s = (const float*)smem;
    const float* w2s = b1s + 64;
#pragma unroll
    for (int mi = 0; mi < 4; mi++) {
#pragma unroll
        for (int rh = 0; rh < 2; rh++) {
            float v = 0.0f;
#pragma unroll
            for (int nj = 0; nj < 4; nj++) {
                int ncol = wn * 32 + nj * 8 + 2 * (lid & 3);
#pragma unroll
                for (int e = 0; e < 2; e++) {
                    float h = acc[mi][nj][rh * 2 + e] + b1s[ncol + e];
                    v += h * normcdff(h) * w2s[ncol + e];
                }
            }
            v += __shfl_xor_sync(0xFFFFFFFFu, v, 1);
            v += __shfl_xor_sync(0xFFFFFFFFu, v, 2);
            if ((lid & 3) == 0) {
                int mrow = m0 + wm * 64 + mi * 16 + rh * 8 + (lid >> 2);
                atomicAdd(out + (size_t)mrow * NQ + q, v);
            }
        }
    }
}

// ---------------------------------------------------------------------------
// Launch
// ---------------------------------------------------------------------------
extern "C" void kernel_launch(void* const* d_in, const int* in_sizes, int n_in,
                              void* d_out, int out_size) {
    const float* x  = (const float*)d_in[0];
    const float* W1 = (const float*)d_in[1];
    const float* b1 = (const float*)d_in[2];
    const float* W2 = (const float*)d_in[3];
    const float* b2 = (const float*)d_in[4];
    float* out = (float*)d_out;
    (void)in_sizes; (void)n_in; (void)out_size;

    cudaFuncSetAttribute(gemm_kernel, cudaFuncAttributeMaxDynamicSharedMemorySize, SMEM_BYTES);

    int n4 = BATCH * HIDDEN / 4;
    prep_x_kernel<<<(n4 + 255) / 256, 256>>>((const float4*)x, n4);
    prep_wf_kernel<<<dim3(2048, 4), 1024>>>(W1);
    init_out_kernel<<<(BATCH * NQ + 255) / 256, 256>>>(out, b2);
    gemm_kernel<<<NTILES, THREADS, SMEM_BYTES>>>(b1, W2, out);
}

// round 10
// speedup vs baseline: 1.0529x; 1.0529x over previous
#include <cuda_runtime.h>
#include <cuda_fp16.h>
#include <cstdint>

// ---------------------------------------------------------------------------
// Problem constants
// ---------------------------------------------------------------------------
#define BATCH    8192
#define HIDDEN   2048
#define NQ       16
#define HALF_DIM 1024

// GEMM tiling: CTA 128(M)x64(N), 4 warps (2Mx2N of 64x32), 4 CTAs/SM.
// BOTH operands fragment-major in gmem -> LDG straight to registers.
// No smem staging, no barriers in the main loop (flat 128-step K pipeline).
#define BM      128
#define BN      64
#define THREADS 128
#define M_TILES (BATCH / BM)            // 64
#define N_TILES (NQ * HALF_DIM / BN)    // 256
#define NTILES  (M_TILES * N_TILES)     // 16384
#define KSTEPS  (HIDDEN / 16)           // 128 k16 steps

// Fragment record strides (bytes)
//   A record (m16,k16): 32 lanes x 16B = 512B; addr = (m16*128 + k16)*512 + lane*16
//   B record (k16,n8):  32 lanes x  8B = 256B; addr = (k16*2048 + n8)*256 + lane*8
#define A_K16_STRIDE 512u
#define A_M16_STRIDE 65536u             // 128 * 512
#define B_N8_STRIDE  256u
#define B_K16_STRIDE 524288u            // 2048 * 256

// fp16 fragment scratch (+pad for the pipeline's final dead prefetch)
__device__ __align__(1024) __half g_Xf[(size_t)BATCH * HIDDEN + 512];        // 32 MB + 1KB
__device__ __align__(1024) __half g_Wf[(size_t)NQ * HALF_DIM * HIDDEN + 8192]; // 64 MB + 16KB

// ---------------------------------------------------------------------------
// Helpers
// ---------------------------------------------------------------------------
__device__ __forceinline__ void mma16816(float* c, const uint32_t* a, uint2 b) {
    asm volatile(
        "mma.sync.aligned.m16n8k16.row.col.f32.f16.f16.f32 "
        "{%0,%1,%2,%3}, {%4,%5,%6,%7}, {%8,%9}, {%0,%1,%2,%3};"
        : "+f"(c[0]), "+f"(c[1]), "+f"(c[2]), "+f"(c[3])
        : "r"(a[0]), "r"(a[1]), "r"(a[2]), "r"(a[3]), "r"(b.x), "r"(b.y));
}

// ---------------------------------------------------------------------------
// Prepass kernels
// ---------------------------------------------------------------------------
// X[b][h] fp32 -> A fragment records for mma.m16n8k16 row-major A:
// record (m16,k16), lane l: r=l>>2, c=(l&3)*2 (relative);
//   a0={A[r][c],A[r][c+1]}, a1={A[r+8][c],...}, a2={A[r][c+8],...}, a3={A[r+8][c+8],...}
__global__ void prep_xf_kernel(const float* __restrict__ x) {
    int rec  = blockIdx.x * 8 + (threadIdx.x >> 5);  // 0..65535
    int lane = threadIdx.x & 31;
    int m16 = rec >> 7;
    int k16 = rec & 127;
    int r = m16 * 16 + (lane >> 2);
    int c = k16 * 16 + ((lane & 3) << 1);
    const float* p  = x + (size_t)r * HIDDEN + c;
    const float* p8 = p + 8 * HIDDEN;
    union { __half2 h; uint32_t u; } r0, r1, r2, r3;
    r0.h = __floats2half2_rn(p[0],  p[1]);
    r1.h = __floats2half2_rn(p8[0], p8[1]);
    r2.h = __floats2half2_rn(p[8],  p[9]);
    r3.h = __floats2half2_rn(p8[8], p8[9]);
    reinterpret_cast<uint4*>(g_Xf)[(size_t)rec * 32 + lane] =
        make_uint4(r0.u, r1.u, r2.u, r3.u);
}

// W1[q][k][n] (n contiguous) -> B fragment records (verified in R9):
// record (k16,n8), lane l: n=l>>2, k pairs at 2(l&3) and 2(l&3)+8.
__global__ void prep_wf_kernel(const float* __restrict__ W1) {
    int n8   = blockIdx.x;                               // 0..2047
    int k16  = blockIdx.y * 32 + (threadIdx.x >> 5);     // 0..127
    int lane = threadIdx.x & 31;
    int q = n8 >> 7;
    int n = ((n8 & 127) << 3) + (lane >> 2);
    const float* src = W1 + (size_t)q * HIDDEN * HALF_DIM + n;
    int kb = (k16 << 4) + ((lane & 3) << 1);
    float v0 = src[(size_t)(kb + 0) * HALF_DIM];
    float v1 = src[(size_t)(kb + 1) * HALF_DIM];
    float v2 = src[(size_t)(kb + 8) * HALF_DIM];
    float v3 = src[(size_t)(kb + 9) * HALF_DIM];
    union { __half2 h; uint32_t u; } r0, r1;
    r0.h = __floats2half2_rn(v0, v1);
    r1.h = __floats2half2_rn(v2, v3);
    reinterpret_cast<uint2*>(g_Wf)[((size_t)k16 * 2048 + n8) * 32 + lane] =
        make_uint2(r0.u, r1.u);
}

__global__ void init_out_kernel(float* __restrict__ out, const float* __restrict__ b2) {
    int i = blockIdx.x * blockDim.x + threadIdx.x;
    if (i < BATCH * NQ) out[i] = b2[i & (NQ - 1)];
}

// ---------------------------------------------------------------------------
// Main GEMM + fused GELU/GEMV epilogue — all-register, barrier-free mainloop
// ---------------------------------------------------------------------------
__device__ __forceinline__ void loadA(uint4* a, const char* Ap) {
#pragma unroll
    for (int mi = 0; mi < 4; mi++)
        a[mi] = *reinterpret_cast<const uint4*>(Ap + mi * A_M16_STRIDE);
}
__device__ __forceinline__ void loadB(uint2* b, const char* Bp) {
#pragma unroll
    for (int nj = 0; nj < 4; nj++)
        b[nj] = *reinterpret_cast<const uint2*>(Bp + nj * B_N8_STRIDE);
}

__global__ void __launch_bounds__(THREADS, 4)
gemm_kernel(const float* __restrict__ b1, const float* __restrict__ W2,
            float* __restrict__ out) {
    __shared__ float par[128];          // b1[0:64] | w2[64:128]
    const int tid = threadIdx.x;
    const int wid = tid >> 5;
    const int lid = tid & 31;
    const int wm  = wid >> 1;           // M slab (64 rows), 0..1
    const int wn  = wid & 1;            // N slab (32 cols), 0..1

    // Supertile swizzle: 8(M) x 16(N) CTAs per 128-CTA group
    int cta    = blockIdx.x;
    int super  = cta >> 7;
    int within = cta & 127;
    int m_tile = (super & 7) * 8 + (within & 7);     // 0..63
    int n_tile = (super >> 3) * 16 + (within >> 3);  // 0..255
    int m0     = m_tile * BM;
    int q      = n_tile >> 4;
    int nn     = (n_tile & 15) * BN;

    // Fragment base pointers (advance by one k16 stride per step)
    const char* Ap = (const char*)g_Xf
                   + (size_t)(m_tile * 8 + wm * 4) * A_M16_STRIDE + lid * 16;
    const char* Bp = (const char*)g_Wf
                   + ((size_t)(n_tile * 8 + wn * 4) * 32 + lid) * 8;

    // Epilogue params (single barrier of the whole kernel)
    {
        int col = tid & 63;
        const float* src = (tid < 64) ? b1 : W2;
        par[tid] = src[q * HALF_DIM + nn + col];
    }
    __syncthreads();

    float acc[4][4][4];
#pragma unroll
    for (int mi = 0; mi < 4; mi++)
#pragma unroll
        for (int nj = 0; nj < 4; nj++)
#pragma unroll
            for (int e = 0; e < 4; e++) acc[mi][nj][e] = 0.0f;

    // Software pipeline: register double-buffer, prefetch distance 1 step.
    uint4 a0[4], a1[4];
    uint2 b0[4], b1f[4];
    loadA(a0, Ap); loadB(b0, Bp);
    Ap += A_K16_STRIDE; Bp += B_K16_STRIDE;

    for (int s = 0; s < KSTEPS; s += 2) {
        // prefetch step s+1
        loadA(a1, Ap); loadB(b1f, Bp);
        Ap += A_K16_STRIDE; Bp += B_K16_STRIDE;
        // mma step s
#pragma unroll
        for (int mi = 0; mi < 4; mi++)
#pragma unroll
            for (int nj = 0; nj < 4; nj++)
                mma16816(acc[mi][nj], reinterpret_cast<uint32_t*>(&a0[mi]), b0[nj]);
        // prefetch step s+2 (final iteration reads into pad; unused)
        loadA(a0, Ap); loadB(b0, Bp);
        Ap += A_K16_STRIDE; Bp += B_K16_STRIDE;
        // mma step s+1
#pragma unroll
        for (int mi = 0; mi < 4; mi++)
#pragma unroll
            for (int nj = 0; nj < 4; nj++)
                mma16816(acc[mi][nj], reinterpret_cast<uint32_t*>(&a1[mi]), b1f[nj]);
    }

    // Epilogue: h = acc + b1; gelu(h) = h * Phi(h); dot with W2; quad-reduce.
    const float* b1s = par;
    const float* w2s = par + 64;
#pragma unroll
    for (int mi = 0; mi < 4; mi++) {
#pragma unroll
        for (int rh = 0; rh < 2; rh++) {
            float v = 0.0f;
#pragma unroll
            for (int nj = 0; nj < 4; nj++) {
                int ncol = wn * 32 + nj * 8 + 2 * (lid & 3);
#pragma unroll
                for (int e = 0; e < 2; e++) {
                    float h = acc[mi][nj][rh * 2 + e] + b1s[ncol + e];
                    v += h * normcdff(h) * w2s[ncol + e];
                }
            }
            v += __shfl_xor_sync(0xFFFFFFFFu, v, 1);
            v += __shfl_xor_sync(0xFFFFFFFFu, v, 2);
            if ((lid & 3) == 0) {
                int mrow = m0 + wm * 64 + mi * 16 + rh * 8 + (lid >> 2);
                atomicAdd(out + (size_t)mrow * NQ + q, v);
            }
        }
    }
}

// ---------------------------------------------------------------------------
// Launch
// ---------------------------------------------------------------------------
extern "C" void kernel_launch(void* const* d_in, const int* in_sizes, int n_in,
                              void* d_out, int out_size) {
    const float* x  = (const float*)d_in[0];
    const float* W1 = (const float*)d_in[1];
    const float* b1 = (const float*)d_in[2];
    const float* W2 = (const float*)d_in[3];
    const float* b2 = (const float*)d_in[4];
    float* out = (float*)d_out;
    (void)in_sizes; (void)n_in; (void)out_size;

    prep_xf_kernel<<<8192, 256>>>(x);
    prep_wf_kernel<<<dim3(2048, 4), 1024>>>(W1);
    init_out_kernel<<<(BATCH * NQ + 255) / 256, 256>>>(out, b2);
    gemm_kernel<<<NTILES, THREADS>>>(b1, W2, out);
}